// round 7
// baseline (speedup 1.0000x reference)
#include <cuda_runtime.h>
#include <cuda_bf16.h>
#include <math.h>
#include <stdint.h>

#define DIM    64
#define NCODES 1024
#define NROWS  65536
#define HW     4096
#define QELEMS 4194304
#define FULL_OUT 71368706
#define DELTA  2e-3f
#define ESTRIDE 144          // bytes per staged row: 128 data + 16 pad (bank = 4r+c)

__device__ float  g_b[NCODES];
__device__ int    g_hist[NCODES];
__device__ double g_loss;
__device__ __align__(16) __nv_bfloat16 g_ebf[NCODES * DIM];

// m16n8k16 bf16 MMA, fp32 accum (baseline PTX, sm_80+)
__device__ __forceinline__ void mma16816(float& d0, float& d1, float& d2, float& d3,
                                         uint32_t a0, uint32_t a1, uint32_t a2, uint32_t a3,
                                         uint32_t b0, uint32_t b1) {
    asm volatile(
        "mma.sync.aligned.m16n8k16.row.col.f32.bf16.bf16.f32 "
        "{%0,%1,%2,%3}, {%4,%5,%6,%7}, {%8,%9}, {%0,%1,%2,%3};"
        : "+f"(d0), "+f"(d1), "+f"(d2), "+f"(d3)
        : "r"(a0), "r"(a1), "r"(a2), "r"(a3), "r"(b0), "r"(b1));
}

// ---------------------------------------------------------------------------
__global__ void init_kernel(const float* __restrict__ emb) {
    int t = blockIdx.x * 128 + threadIdx.x;       // 0..1023 = code
    g_hist[t] = 0;
    if (t == 0) g_loss = 0.0;
    const float4* e4 = (const float4*)(emb + t * DIM);
    float4 v[16];
#pragma unroll
    for (int i = 0; i < 16; ++i) v[i] = e4[i];
    float s = 0.f;
#pragma unroll
    for (int i = 0; i < 16; ++i) {                // sequential-d rounding chain
        s = __fadd_rn(s, __fmul_rn(v[i].x, v[i].x));
        s = __fadd_rn(s, __fmul_rn(v[i].y, v[i].y));
        s = __fadd_rn(s, __fmul_rn(v[i].z, v[i].z));
        s = __fadd_rn(s, __fmul_rn(v[i].w, v[i].w));
    }
    g_b[t] = s;
    uint32_t* eb = (uint32_t*)(g_ebf + (size_t)t * DIM);
#pragma unroll
    for (int i = 0; i < 16; ++i) {
        __nv_bfloat162 h0 = __floats2bfloat162_rn(v[i].x, v[i].y);
        __nv_bfloat162 h1 = __floats2bfloat162_rn(v[i].z, v[i].w);
        eb[2 * i]     = *(uint32_t*)&h0;
        eb[2 * i + 1] = *(uint32_t*)&h1;
    }
}

// ---------------------------------------------------------------------------
__global__ void __launch_bounds__(128) vq_kernel(
    const float* __restrict__ xin, const float* __restrict__ emb,
    float* __restrict__ oq, float* __restrict__ oenc, float* __restrict__ oidx)
{
    __shared__ __align__(16) uint8_t Xbf[128 * ESTRIDE];    // 18432 B, bf16 rows
    __shared__ __align__(16) uint8_t Ech[2][64 * ESTRIDE];  // 18432 B, E chunks
    __shared__ float s_a[128];
    __shared__ float s_b[NCODES];
    __shared__ int   scand[128][12];
    __shared__ int   scnt[128];
    __shared__ int   sidx[128];

    int tid = threadIdx.x;                 // 128 threads; prologue/epilogue: tid=row
    int n0  = blockIdx.x * 128;
    int img = n0 >> 12, hw0 = n0 & 4095;
    const float* gx = xin + (size_t)img * (DIM * HW) + hw0 + tid;

    // ---- prologue: exact a (reference chain), bf16 X tile, stage b + E0 ----
    {
        float a = 0.f;
#pragma unroll
        for (int d = 0; d < DIM; d += 2) {
            float v0 = gx[d * HW], v1 = gx[(d + 1) * HW];
            a = __fadd_rn(a, __fmul_rn(v0, v0));
            a = __fadd_rn(a, __fmul_rn(v1, v1));
            __nv_bfloat162 h = __floats2bfloat162_rn(v0, v1);
            *(uint32_t*)(Xbf + tid * ESTRIDE + d * 2) = *(uint32_t*)&h;
        }
        s_a[tid] = a;
        scnt[tid] = 0;
#pragma unroll
        for (int k = 0; k < 8; ++k) s_b[tid + k * 128] = g_b[tid + k * 128];
        const uint4* src = (const uint4*)g_ebf;   // chunk 0 (64 codes x 128 B)
#pragma unroll
        for (int k = 0; k < 4; ++k) {
            int j = tid + k * 128;
            *(uint4*)(Ech[0] + (j >> 3) * ESTRIDE + (j & 7) * 16) = src[j];
        }
    }
    __syncthreads();

    // ---- fragment setup ----
    int lane   = tid & 31, w = tid >> 5;
    int lane_r = lane >> 2, lane_c = lane & 3;

    uint32_t af[2][4][4];                  // [row-tile][kstep][4 regs]
#pragma unroll
    for (int rt = 0; rt < 2; ++rt)
#pragma unroll
        for (int s = 0; s < 4; ++s) {
            int r0 = w * 32 + rt * 16 + lane_r;
            int kb = (s * 16 + 2 * lane_c) * 2;  // byte offset of k-pair
            af[rt][s][0] = *(uint32_t*)(Xbf + r0 * ESTRIDE + kb);
            af[rt][s][1] = *(uint32_t*)(Xbf + (r0 + 8) * ESTRIDE + kb);
            af[rt][s][2] = *(uint32_t*)(Xbf + r0 * ESTRIDE + kb + 16);
            af[rt][s][3] = *(uint32_t*)(Xbf + (r0 + 8) * ESTRIDE + kb + 16);
        }
    float a_r[4];
#pragma unroll
    for (int rs = 0; rs < 4; ++rs)
        a_r[rs] = s_a[w * 32 + (rs >> 1) * 16 + lane_r + (rs & 1) * 8];

    const float INF = __int_as_float(0x7f800000);
    float amin_l[4];
    float sc[4][4];
    int   cd[4][4];
    bool  ovf = false;
#pragma unroll
    for (int rs = 0; rs < 4; ++rs) {
        amin_l[rs] = INF;
#pragma unroll
        for (int j = 0; j < 4; ++j) { sc[rs][j] = INF; cd[rs][j] = 0; }
    }

    // ---- main loop: 16 chunks of 64 codes ----
    for (int c = 0; c < 16; ++c) {
        uint4 pf[4];
        if (c < 15) {
            const uint4* src = (const uint4*)(g_ebf + (size_t)(c + 1) * 64 * DIM);
#pragma unroll
            for (int k = 0; k < 4; ++k) pf[k] = src[tid + k * 128];
        }
        const uint8_t* EB = Ech[c & 1];
#pragma unroll 2
        for (int ct = 0; ct < 8; ++ct) {           // 8-code tiles
            uint32_t bf_[4][2];
#pragma unroll
            for (int s = 0; s < 4; ++s) {
                const uint8_t* p = EB + (ct * 8 + lane_r) * ESTRIDE
                                      + (s * 16 + 2 * lane_c) * 2;
                bf_[s][0] = *(uint32_t*)p;
                bf_[s][1] = *(uint32_t*)(p + 16);
            }
            int col0 = c * 64 + ct * 8 + 2 * lane_c;
            float b0 = s_b[col0], b1 = s_b[col0 + 1];
#pragma unroll
            for (int rt = 0; rt < 2; ++rt) {
                float d0 = 0.f, d1 = 0.f, d2 = 0.f, d3 = 0.f;
#pragma unroll
                for (int s = 0; s < 4; ++s)
                    mma16816(d0, d1, d2, d3,
                             af[rt][s][0], af[rt][s][1], af[rt][s][2], af[rt][s][3],
                             bf_[s][0], bf_[s][1]);
                // scores: (d0,d1)=row g; (d2,d3)=row g+8; cols col0,col0+1
#pragma unroll
                for (int h = 0; h < 4; ++h) {
                    int rs = rt * 2 + (h >> 1);
                    float m  = (h == 0) ? d0 : (h == 1) ? d1 : (h == 2) ? d2 : d3;
                    float ab = __fadd_rn(a_r[rs], (h & 1) ? b1 : b0);
                    float sv = __fmaf_rn(-2.f, m, ab);
                    if (sv < amin_l[rs] + DELTA) {
                        if (sv < amin_l[rs]) amin_l[rs] = sv;
                        bool ins = false;
#pragma unroll
                        for (int j = 0; j < 4; ++j)
                            if (!ins && sc[rs][j] >= amin_l[rs] + DELTA) {
                                sc[rs][j] = sv;
                                cd[rs][j] = col0 + (h & 1);
                                ins = true;
                            }
                        if (!ins) ovf = true;
                    }
                }
            }
        }
        if (c < 15) {
            uint8_t* dst = Ech[(c + 1) & 1];
#pragma unroll
            for (int k = 0; k < 4; ++k) {
                int j = tid + k * 128;
                *(uint4*)(dst + (j >> 3) * ESTRIDE + (j & 7) * 16) = pf[k];
            }
        }
        __syncthreads();
    }

    // ---- quad-reduce row minima, dump surviving candidates to smem ----
#pragma unroll
    for (int rs = 0; rs < 4; ++rs) {
        float g = amin_l[rs];
        g = fminf(g, __shfl_xor_sync(0xffffffffu, g, 1));
        g = fminf(g, __shfl_xor_sync(0xffffffffu, g, 2));
        int row = w * 32 + (rs >> 1) * 16 + lane_r + (rs & 1) * 8;
#pragma unroll
        for (int j = 0; j < 4; ++j)
            if (sc[rs][j] < g + DELTA) {
                int p = atomicAdd(&scnt[row], 1);
                if (p < 12) scand[row][p] = cd[rs][j];
            }
        if (ovf) atomicAdd(&scnt[row], 1000);      // force full-scan fallback
    }
    __syncthreads();

    // ---- exact rescore (bitwise-identical chain), thread = row ----
    float x[DIM];
#pragma unroll
    for (int d = 0; d < DIM; ++d) x[d] = gx[d * HW];
    float aex = s_a[tid];
    int   cnt = scnt[tid];
    unsigned long long bestk = 0xFFFFFFFFFFFFFFFFull;
    if (cnt <= 12) {
        for (int q = 0; q < cnt; ++q) {
            int code = scand[tid][q];
            const float* e = emb + code * DIM;
            float m = 0.f;
#pragma unroll
            for (int d = 0; d < DIM; ++d) m = __fmaf_rn(x[d], e[d], m);
            float s = __fadd_rn(__fadd_rn(aex, s_b[code]), -2.0f * m);
            unsigned long long key =
                ((unsigned long long)__float_as_uint(s) << 32) | (unsigned)code;
            if (key < bestk) bestk = key;
        }
    } else {                                        // pathological fallback
        for (int code = 0; code < NCODES; ++code) {
            const float* e = emb + code * DIM;
            float m = 0.f;
#pragma unroll
            for (int d = 0; d < DIM; ++d) m = __fmaf_rn(x[d], e[d], m);
            float s = __fadd_rn(__fadd_rn(aex, s_b[code]), -2.0f * m);
            unsigned long long key =
                ((unsigned long long)__float_as_uint(s) << 32) | (unsigned)code;
            if (key < bestk) bestk = key;
        }
    }
    int idx = (int)(bestk & 0xFFFFFFFFu);

    sidx[tid] = idx;
    atomicAdd(&g_hist[idx], 1);
    if (oidx) oidx[n0 + tid] = (float)idx;
    {
        const float* e = emb + idx * DIM;
        float ls = 0.f;
#pragma unroll
        for (int d = 0; d < DIM; ++d) {
            float dif = e[d] - x[d];
            ls = __fmaf_rn(dif, dif, ls);
        }
        double lsum = ls;
#pragma unroll
        for (int off = 16; off; off >>= 1)
            lsum += __shfl_down_sync(0xffffffffu, lsum, off);
        if ((tid & 31) == 0) atomicAdd(&g_loss, lsum);
    }
    __syncthreads();

    // ---- quantized_st, NCHW (coalesced 128-float runs per channel) ----
    for (int i = tid; i < DIM * 128; i += 128) {
        int cc = i >> 7, row = i & 127;
        oq[(size_t)img * (DIM * HW) + cc * HW + hw0 + row] = emb[sidx[row] * DIM + cc];
    }

    // ---- one-hot encodings (base only 8B-aligned -> float2) ----
    if (oenc) {
        float2* enc2 = (float2*)oenc;
        for (int i = tid; i < 128 * 512; i += 128) {
            int row = i >> 9, jj = i & 511;
            int id = sidx[row];
            float2 z = make_float2(0.f, 0.f);
            if ((id >> 1) == jj) ((float*)&z)[id & 1] = 1.0f;
            enc2[(size_t)(n0 + row) * 512 + jj] = z;
        }
    }
}

// ---------------------------------------------------------------------------
__global__ void finalize_kernel(float* __restrict__ oloss, float* __restrict__ operp) {
    int t = threadIdx.x;                           // 1024 threads
    double p = (double)g_hist[t] / 65536.0;
    double h = -p * log(p + 1e-10);
    __shared__ double sh[32];
#pragma unroll
    for (int off = 16; off; off >>= 1) h += __shfl_down_sync(0xffffffffu, h, off);
    if ((t & 31) == 0) sh[t >> 5] = h;
    __syncthreads();
    if (t < 32) {
        double v = sh[t];
#pragma unroll
        for (int off = 16; off; off >>= 1) v += __shfl_down_sync(0xffffffffu, v, off);
        if (t == 0) {
            operp[0] = (float)exp(v);
            oloss[0] = (float)(1.25 * (g_loss / (double)QELEMS));
        }
    }
}

// ---------------------------------------------------------------------------
extern "C" void kernel_launch(void* const* d_in, const int* in_sizes, int n_in,
                              void* d_out, int out_size) {
    const float* xin = (const float*)d_in[0];
    const float* emb = (const float*)d_in[1];
    if (n_in >= 2 && in_sizes[0] == NCODES * DIM && in_sizes[1] == QELEMS) {
        xin = (const float*)d_in[1];
        emb = (const float*)d_in[0];
    }
    float* out  = (float*)d_out;
    bool   full = (out_size >= FULL_OUT);
    float* o_q   = full ? out + 1 : out;
    float* o_enc = full ? out + (size_t)QELEMS + 2 : nullptr;
    float* o_idx = full ? out + (size_t)QELEMS + 2 + (size_t)NROWS * NCODES : nullptr;

    init_kernel<<<8, 128>>>(emb);
    vq_kernel<<<512, 128>>>(xin, emb, o_q, o_enc, o_idx);
    if (full) finalize_kernel<<<1, 1024>>>(out, out + QELEMS + 1);
}

// round 8
// speedup vs baseline: 1.5443x; 1.5443x over previous
#include <cuda_runtime.h>
#include <math.h>
#include <stdint.h>

#define DIM    64
#define NCODES 1024
#define NROWS  65536
#define HW     4096
#define QELEMS 4194304
#define FULL_OUT 71368706

#define XINV     23.0909090909f                    // 127/5.5
#define EINV     130048.0f                         // 1024*127
#define NEG2SXSE (-2.0f / (23.0909090909f * 130048.0f))

__device__ float  g_b[NCODES];
__device__ int    g_hist[NCODES];
__device__ double g_loss;
__device__ __align__(16) int g_eq[NCODES * 16];    // [chunk][kw][codeL] packed int8x4

// ---------------------------------------------------------------------------
__global__ void init_kernel(const float* __restrict__ emb) {
    int t = blockIdx.x * 128 + threadIdx.x;        // code 0..1023
    g_hist[t] = 0;
    if (t == 0) g_loss = 0.0;
    const float4* e4 = (const float4*)(emb + t * DIM);
    float4 v[16];
#pragma unroll
    for (int i = 0; i < 16; ++i) v[i] = e4[i];
    float s = 0.f;
#pragma unroll
    for (int i = 0; i < 16; ++i) {                 // reference rounding chain
        s = __fadd_rn(s, __fmul_rn(v[i].x, v[i].x));
        s = __fadd_rn(s, __fmul_rn(v[i].y, v[i].y));
        s = __fadd_rn(s, __fmul_rn(v[i].z, v[i].z));
        s = __fadd_rn(s, __fmul_rn(v[i].w, v[i].w));
    }
    g_b[t] = s;
    int c = t >> 6, cl = t & 63;                   // int8 pack: dims 4kw..4kw+3
#pragma unroll
    for (int kw = 0; kw < 16; ++kw) {
        int q0 = max(-127, min(127, __float2int_rn(v[kw].x * EINV)));
        int q1 = max(-127, min(127, __float2int_rn(v[kw].y * EINV)));
        int q2 = max(-127, min(127, __float2int_rn(v[kw].z * EINV)));
        int q3 = max(-127, min(127, __float2int_rn(v[kw].w * EINV)));
        g_eq[c * 1024 + kw * 64 + cl] =
            (q0 & 255) | ((q1 & 255) << 8) | ((q2 & 255) << 16) | ((q3 & 255) << 24);
    }
}

// exact score key (bitwise-identical to the R4 chain)
__device__ __forceinline__ unsigned long long exact_key(
    const float* Xs, int row, const float* __restrict__ emb, float aex, int code)
{
    const float* e = emb + code * DIM;
    float m = 0.f;
#pragma unroll
    for (int d = 0; d < DIM; ++d) m = __fmaf_rn(Xs[d * 128 + row], e[d], m);
    float s = __fadd_rn(__fadd_rn(aex, g_b[code]), -2.0f * m);
    return ((unsigned long long)__float_as_uint(s) << 32) | (unsigned)code;
}

// ---------------------------------------------------------------------------
__global__ void __launch_bounds__(256, 2) vq_kernel(
    const float* __restrict__ xin, const float* __restrict__ emb,
    float* __restrict__ oq, float* __restrict__ oenc, float* __restrict__ oidx)
{
    __shared__ __align__(16) float Xs[DIM * 128];       // 32 KB fp32 [d][row]
    __shared__ __align__(16) int   Xq[16 * 128];        //  8 KB int8x4 [kw][row]
    __shared__ __align__(16) int   EqS[1024];           //  4 KB one E chunk [kw][codeL]
    __shared__ unsigned long long  keys[128];
    __shared__ int                 sidx[128];

    int tid = threadIdx.x;
    int tr  = tid & 31;               // rows tr*4 .. tr*4+3
    int tc  = tid >> 5;               // codes tc*8 .. tc*8+7 per chunk
    int n0  = blockIdx.x * 128;
    int img = n0 >> 12, hw0 = n0 & 4095;
    const float* gbase = xin + (size_t)img * (DIM * HW) + hw0;

    // stage X tile fp32 (coalesced) + chunk 0 of E
    for (int i = tid; i < DIM * 128; i += 256) {
        int d = i >> 7, r = i & 127;
        Xs[i] = gbase[d * HW + r];
    }
#pragma unroll
    for (int k = 0; k < 4; ++k) EqS[tid + k * 256] = g_eq[tid + k * 256];
    __syncthreads();

    // per-row exact a (reference chain) + error budget + outlier flag
    float a[4], dlt[4];
    bool  exa[4];
#pragma unroll
    for (int rs = 0; rs < 4; ++rs) {
        int row = tr * 4 + rs;
        float s = 0.f, sa = 0.f, ma = 0.f;
#pragma unroll
        for (int d = 0; d < DIM; ++d) {
            float v = Xs[d * 128 + row];
            s  = __fadd_rn(s, __fmul_rn(v, v));
            sa += fabsf(v);
            ma  = fmaxf(ma, fabsf(v));
        }
        a[rs]   = s;
        dlt[rs] = 4.0f * (1.353e-3f + 3.85e-6f * sa + 2e-5f);
        exa[rs] = (ma > 5.5f);
    }

    // pack x -> int8x4 [kw][row]
    for (int i = tid; i < 16 * 128; i += 256) {
        int kw = i >> 7, row = i & 127;
        int q[4];
#pragma unroll
        for (int t = 0; t < 4; ++t) {
            float xv = Xs[(kw * 4 + t) * 128 + row];
            q[t] = max(-127, min(127, __float2int_rn(xv * XINV)));
        }
        Xq[kw * 128 + row] =
            (q[0] & 255) | ((q[1] & 255) << 8) | ((q[2] & 255) << 16) | ((q[3] & 255) << 24);
    }
    __syncthreads();

    const float INF = __int_as_float(0x7f800000);
    float umin[4], sc[4][3];
    int   cd[4][3];
    bool  ovf[4];
#pragma unroll
    for (int rs = 0; rs < 4; ++rs) {
        umin[rs] = INF; ovf[rs] = false;
#pragma unroll
        for (int j = 0; j < 3; ++j) { sc[rs][j] = INF; cd[rs][j] = 0; }
    }

    // ---- main loop: 16 chunks of 64 codes, int8 dp4a prefilter ----
    for (int c = 0; c < 16; ++c) {
        int pf[4];
        if (c < 15) {                               // prefetch next chunk to regs
            const int* src = g_eq + (c + 1) * 1024;
#pragma unroll
            for (int k = 0; k < 4; ++k) pf[k] = src[tid + k * 256];
        }
        int acc[4][8];
#pragma unroll
        for (int r = 0; r < 4; ++r)
#pragma unroll
            for (int j = 0; j < 8; ++j) acc[r][j] = 0;

#pragma unroll 4
        for (int kw = 0; kw < 16; ++kw) {
            int4 xw = *(const int4*)&Xq[kw * 128 + tr * 4];
            int4 e0 = *(const int4*)&EqS[kw * 64 + tc * 8];
            int4 e1 = *(const int4*)&EqS[kw * 64 + tc * 8 + 4];
            const int* xp = (const int*)&xw;
            const int* ep[2] = { (const int*)&e0, (const int*)&e1 };
#pragma unroll
            for (int j = 0; j < 8; ++j) {
                int ev = ep[j >> 2][j & 3];
                acc[0][j] = __dp4a(xp[0], ev, acc[0][j]);
                acc[1][j] = __dp4a(xp[1], ev, acc[1][j]);
                acc[2][j] = __dp4a(xp[2], ev, acc[2][j]);
                acc[3][j] = __dp4a(xp[3], ev, acc[3][j]);
            }
        }
        __syncthreads();                            // EqS reads done
        if (c < 15) {
#pragma unroll
            for (int k = 0; k < 4; ++k) EqS[tid + k * 256] = pf[k];
        }

        // approx scores + candidate collection (proven R7 rule)
#pragma unroll
        for (int j = 0; j < 8; ++j) {
            int code = c * 64 + tc * 8 + j;
            float bb = __ldg(&g_b[code]);
#pragma unroll
            for (int rs = 0; rs < 4; ++rs) {
                float u = __fmaf_rn((float)acc[rs][j], NEG2SXSE, bb);
                if (u < umin[rs] + dlt[rs]) {
                    if (u < umin[rs]) umin[rs] = u;
                    bool ins = false;
#pragma unroll
                    for (int q = 0; q < 3; ++q)
                        if (!ins && sc[rs][q] >= umin[rs] + dlt[rs]) {
                            sc[rs][q] = u; cd[rs][q] = code; ins = true;
                        }
                    if (!ins) ovf[rs] = true;
                }
            }
        }
        __syncthreads();                            // EqS(c+1) staged
    }

    // ---- exact rescore -> packed-key row argmin (first-occurrence ties) ----
    if (tid < 128) keys[tid] = 0xFFFFFFFFFFFFFFFFull;
    __syncthreads();
#pragma unroll
    for (int rs = 0; rs < 4; ++rs) {
        int row = tr * 4 + rs;
        unsigned long long bk = 0xFFFFFFFFFFFFFFFFull;
        if (exa[rs] || ovf[rs]) {                   // rare: exact scan of own 128 codes
            for (int c16 = 0; c16 < 16; ++c16)
#pragma unroll
                for (int j = 0; j < 8; ++j) {
                    unsigned long long k =
                        exact_key(Xs, row, emb, a[rs], c16 * 64 + tc * 8 + j);
                    if (k < bk) bk = k;
                }
        } else {
#pragma unroll
            for (int q = 0; q < 3; ++q)
                if (sc[rs][q] < umin[rs] + dlt[rs]) {
                    unsigned long long k = exact_key(Xs, row, emb, a[rs], cd[rs][q]);
                    if (k < bk) bk = k;
                }
        }
        atomicMin(&keys[row], bk);
    }
    __syncthreads();

    double lsum = 0.0;
    if (tid < 128) {
        int idx = (int)(keys[tid] & 0xFFFFFFFFull);
        sidx[tid] = idx;
        atomicAdd(&g_hist[idx], 1);
        if (oidx) oidx[n0 + tid] = (float)idx;
        const float* e = emb + idx * DIM;
        float s = 0.f;
#pragma unroll
        for (int d = 0; d < DIM; ++d) {
            float dif = e[d] - Xs[d * 128 + tid];
            s = __fmaf_rn(dif, dif, s);
        }
        lsum = (double)s;
    }
#pragma unroll
    for (int off = 16; off; off >>= 1)
        lsum += __shfl_down_sync(0xffffffffu, lsum, off);
    if (tid < 128 && (tid & 31) == 0) atomicAdd(&g_loss, lsum);
    __syncthreads();

    // quantized_st, NCHW (coalesced 128-float runs per channel)
    for (int i = tid; i < DIM * 128; i += 256) {
        int cc = i >> 7, row = i & 127;
        oq[(size_t)img * (DIM * HW) + cc * HW + hw0 + row] = emb[sidx[row] * DIM + cc];
    }

    // one-hot encodings (base only 8B-aligned -> float2)
    if (oenc) {
        float2* enc2 = (float2*)oenc;
        for (int i = tid; i < 128 * 512; i += 256) {
            int row = i >> 9, jj = i & 511;
            int id = sidx[row];
            float2 z = make_float2(0.f, 0.f);
            if ((id >> 1) == jj) ((float*)&z)[id & 1] = 1.0f;
            enc2[(size_t)(n0 + row) * 512 + jj] = z;
        }
    }
}

// ---------------------------------------------------------------------------
__global__ void finalize_kernel(float* __restrict__ oloss, float* __restrict__ operp) {
    int t = threadIdx.x;                            // 1024 threads
    double p = (double)g_hist[t] / 65536.0;
    double h = -p * log(p + 1e-10);
    __shared__ double sh[32];
#pragma unroll
    for (int off = 16; off; off >>= 1) h += __shfl_down_sync(0xffffffffu, h, off);
    if ((t & 31) == 0) sh[t >> 5] = h;
    __syncthreads();
    if (t < 32) {
        double v = sh[t];
#pragma unroll
        for (int off = 16; off; off >>= 1) v += __shfl_down_sync(0xffffffffu, v, off);
        if (t == 0) {
            operp[0] = (float)exp(v);
            oloss[0] = (float)(1.25 * (g_loss / (double)QELEMS));
        }
    }
}

// ---------------------------------------------------------------------------
extern "C" void kernel_launch(void* const* d_in, const int* in_sizes, int n_in,
                              void* d_out, int out_size) {
    const float* xin = (const float*)d_in[0];
    const float* emb = (const float*)d_in[1];
    if (n_in >= 2 && in_sizes[0] == NCODES * DIM && in_sizes[1] == QELEMS) {
        xin = (const float*)d_in[1];
        emb = (const float*)d_in[0];
    }
    float* out  = (float*)d_out;
    bool   full = (out_size >= FULL_OUT);
    float* o_q   = full ? out + 1 : out;
    float* o_enc = full ? out + (size_t)QELEMS + 2 : nullptr;
    float* o_idx = full ? out + (size_t)QELEMS + 2 + (size_t)NROWS * NCODES : nullptr;

    init_kernel<<<8, 128>>>(emb);
    vq_kernel<<<512, 256>>>(xin, emb, o_q, o_enc, o_idx);
    if (full) finalize_kernel<<<1, 1024>>>(out, out + QELEMS + 1);
}